// round 13
// baseline (speedup 1.0000x reference)
#include <cuda_runtime.h>

#define NBLK 128
#define WPB  16       // warps per block -> 4 warps per SMSP
#define TT   512
#define HH   32

typedef unsigned long long u64;

__device__ __forceinline__ u64 pk2(float a, float b) {
    u64 r; asm("mov.b64 %0,{%1,%2};" : "=l"(r) : "f"(a), "f"(b)); return r;
}
__device__ __forceinline__ void upk2(u64 v, float& a, float& b) {
    asm("mov.b64 {%0,%1},%2;" : "=f"(a), "=f"(b) : "l"(v));
}
__device__ __forceinline__ u64 ffma2(u64 a, u64 b, u64 c) {
    u64 d; asm("fma.rn.f32x2 %0,%1,%2,%3;" : "=l"(d) : "l"(a), "l"(b), "l"(c)); return d;
}
__device__ __forceinline__ u64 fmul2(u64 a, u64 b) {
    u64 d; asm("mul.rn.f32x2 %0,%1,%2;" : "=l"(d) : "l"(a), "l"(b)); return d;
}
__device__ __forceinline__ u64 fadd2(u64 a, u64 b) {
    u64 d; asm("add.rn.f32x2 %0,%1,%2;" : "=l"(d) : "l"(a), "l"(b)); return d;
}
__device__ __forceinline__ float ex2f(float x) {
    float y; asm("ex2.approx.f32 %0,%1;" : "=f"(y) : "f"(x)); return y;
}
__device__ __forceinline__ float rcpf(float x) {
    float y; asm("rcp.approx.f32 %0,%1;" : "=f"(y) : "f"(x)); return y;
}
__device__ __forceinline__ float tanh_mufu(float x) {
    float y; asm("tanh.approx.f32 %0,%1;" : "=f"(y) : "f"(x)); return y;
}
// volatile LDS.128: pinned program order (replaces __syncwarp for h ping-pong)
__device__ __forceinline__ void lds_u64x2_v(const float* p, u64& a, u64& b) {
    unsigned sa = (unsigned)__cvta_generic_to_shared((const void*)p);
    asm volatile("ld.volatile.shared.v2.b64 {%0,%1}, [%2];" : "=l"(a), "=l"(b) : "r"(sa));
}
__device__ __forceinline__ void sts_f32_v(float* p, float v) {
    unsigned sa = (unsigned)__cvta_generic_to_shared((void*)p);
    asm volatile("st.volatile.shared.f32 [%0], %1;" :: "r"(sa), "f"(v) : "memory");
}
// accurate versions for the one-off backward step + output
__device__ __forceinline__ float sigm(float v) {
    return rcpf(1.0f + ex2f(v * -1.4426950408889634f));
}
__device__ __forceinline__ float tanhfast(float v) {
    float s = rcpf(1.0f + ex2f(v * -2.8853900817779268f));
    return fmaf(2.0f, s, -1.0f);
}

__global__ void __launch_bounds__(WPB * 32, 1)
gru_bidir_kernel(const float* __restrict__ x,
                 const float* __restrict__ Wihf, const float* __restrict__ Whhf,
                 const float* __restrict__ bihf, const float* __restrict__ bhhf,
                 const float* __restrict__ Wihb, const float* __restrict__ Whhb,
                 const float* __restrict__ bihb, const float* __restrict__ bhhb,
                 const float* __restrict__ W1,  const float* __restrict__ b1,
                 const float* __restrict__ W2,  const float* __restrict__ b2,
                 float* __restrict__ out)
{
    __shared__ float xs[WPB][TT];                          // 32 KB: x staged, 1 batch/warp
    __shared__ __align__(16) float hbuf[WPB][2][HH];       // ping-pong hidden (read as u64x2)
    __shared__ __align__(16) float vbuf[WPB][2 * HH];      // concat(h_f, h_b) for MLP
    __shared__ float  w1s[16 * 65];                        // padded stride 65 -> conflict-free
    __shared__ float  b1s[16], w2s[16];

    const int tid  = threadIdx.x;
    const int lane = tid & 31;
    const int warp = tid >> 5;
    const int bb   = blockIdx.x * WPB + warp;  // batch row owned by this warp
    const int j    = lane;                     // hidden dim owned by this lane

    // ---- stage MLP weights (block-wide) ----
    for (int i = tid; i < 16 * 64; i += WPB * 32) {
        int u = i >> 6, k = i & 63;
        w1s[u * 65 + k] = W1[i];
    }
    if (tid < 16) { b1s[tid] = b1[tid]; w2s[tid] = W2[tid]; }

    // ---- stage this warp's x row ----
    for (int i = lane; i < TT; i += 32)
        xs[warp][i] = x[bb * TT + i];

    // ---- load recurrent weights, K-packed into f32x2 pairs.
    //      r,z rows PRE-SCALED by 0.5: sigma(v) = 0.5 + 0.5*tanh(v/2) via MUFU.TANH.
    //      n rows raw: n = tanh(v) via MUFU.TANH. ----
    u64 wr[16], wz[16], wn[16];
    {
        const float2* pr = (const float2*)(Whhf + (j)      * HH);
        const float2* pz = (const float2*)(Whhf + (j + 32) * HH);
        const float2* pn = (const float2*)(Whhf + (j + 64) * HH);
#pragma unroll
        for (int k = 0; k < 16; k++) {
            float2 t0 = pr[k]; wr[k] = pk2(t0.x * 0.5f, t0.y * 0.5f);
            float2 t1 = pz[k]; wz[k] = pk2(t1.x * 0.5f, t1.y * 0.5f);
            float2 t2 = pn[k]; wn[k] = pk2(t2.x, t2.y);
        }
    }
    const float wxr = Wihf[j] * 0.5f, wxz = Wihf[j + 32] * 0.5f, wxn = Wihf[j + 64];
    const float br   = (bihf[j]      + bhhf[j])      * 0.5f;
    const float bz   = (bihf[j + 32] + bhhf[j + 32]) * 0.5f;
    const float bn_i = bihf[j + 64];     // input-side n bias (outside r*)
    const float bn_h = bhhf[j + 64];     // hidden-side n bias (inside r*)

    // ---- init hidden state ----
    float h = 0.f;
    hbuf[warp][0][j] = 0.f;
    __syncwarp();      // orders xs staging + h init before the loop

    const float* xp = &xs[warp][0];
    float* const hb0 = &hbuf[warp][0][0];
    float* const hb1 = &hbuf[warp][1][0];

    // ================= forward GRU scan (unrolled x2 over ping-pong) =================
#pragma unroll 1
    for (int t = 0; t < TT; t += 2) {
#pragma unroll
        for (int half = 0; half < 2; half++) {
            const float* hfp = half ? hb1 : hb0;
            float*       hwp = half ? hb0 : hb1;
            float xv = xp[t + half];
            float sr = fmaf(xv, wxr, br);     // scaled 0.5
            float sz = fmaf(xv, wxz, bz);     // scaled 0.5
            float sn = fmaf(xv, wxn, bn_i);   // raw

            u64 p0, p1, q0, q1;

            // ======== PHASE 1: r and z chains (4 sub-chains; h shared in slot 1
            //          by adjacent FFMA2 pairs -> operand-reuse eligible) ========
            lds_u64x2_v(hfp + 0, p0, p1);
            lds_u64x2_v(hfp + 4, q0, q1);
            u64 ara = ffma2(p0, wr[0], pk2(sr, 0.f));
            u64 aza = ffma2(p0, wz[0], pk2(sz, 0.f));
            u64 arb = fmul2(p1, wr[1]);
            u64 azb = fmul2(p1, wz[1]);
            lds_u64x2_v(hfp + 8, p0, p1);
            ara = ffma2(q0, wr[2], ara);  aza = ffma2(q0, wz[2], aza);
            arb = ffma2(q1, wr[3], arb);  azb = ffma2(q1, wz[3], azb);
            lds_u64x2_v(hfp + 12, q0, q1);
            ara = ffma2(p0, wr[4], ara);  aza = ffma2(p0, wz[4], aza);
            arb = ffma2(p1, wr[5], arb);  azb = ffma2(p1, wz[5], azb);
            lds_u64x2_v(hfp + 16, p0, p1);
            ara = ffma2(q0, wr[6], ara);  aza = ffma2(q0, wz[6], aza);
            arb = ffma2(q1, wr[7], arb);  azb = ffma2(q1, wz[7], azb);
            lds_u64x2_v(hfp + 20, q0, q1);
            ara = ffma2(p0, wr[8], ara);  aza = ffma2(p0, wz[8], aza);
            arb = ffma2(p1, wr[9], arb);  azb = ffma2(p1, wz[9], azb);
            lds_u64x2_v(hfp + 24, p0, p1);
            ara = ffma2(q0, wr[10], ara); aza = ffma2(q0, wz[10], aza);
            arb = ffma2(q1, wr[11], arb); azb = ffma2(q1, wz[11], azb);
            lds_u64x2_v(hfp + 28, q0, q1);
            ara = ffma2(p0, wr[12], ara); aza = ffma2(p0, wz[12], aza);
            arb = ffma2(p1, wr[13], arb); azb = ffma2(p1, wz[13], azb);
            ara = ffma2(q0, wr[14], ara); aza = ffma2(q0, wz[14], aza);
            arb = ffma2(q1, wr[15], arb); azb = ffma2(q1, wz[15], azb);

            // fold r,z sums; launch BOTH MUFUs now -> retire under phase 2
            float lo, hi;
            u64 rs = fadd2(ara, arb);
            u64 zs = fadd2(aza, azb);
            upk2(rs, lo, hi); float tr = tanh_mufu(lo + hi);
            upk2(zs, lo, hi); float tz = tanh_mufu(lo + hi);

            // ======== PHASE 2: n chain (2 sub-chains) ========
            lds_u64x2_v(hfp + 0, p0, p1);
            lds_u64x2_v(hfp + 4, q0, q1);
            u64 ana = ffma2(p0, wn[0], pk2(bn_h, 0.f));
            u64 anb = fmul2(p1, wn[1]);
            lds_u64x2_v(hfp + 8, p0, p1);
            ana = ffma2(q0, wn[2], ana);
            anb = ffma2(q1, wn[3], anb);
            lds_u64x2_v(hfp + 12, q0, q1);
            ana = ffma2(p0, wn[4], ana);
            anb = ffma2(p1, wn[5], anb);
            lds_u64x2_v(hfp + 16, p0, p1);
            ana = ffma2(q0, wn[6], ana);
            anb = ffma2(q1, wn[7], anb);
            lds_u64x2_v(hfp + 20, q0, q1);
            ana = ffma2(p0, wn[8], ana);
            anb = ffma2(p1, wn[9], anb);
            lds_u64x2_v(hfp + 24, p0, p1);
            ana = ffma2(q0, wn[10], ana);
            anb = ffma2(q1, wn[11], anb);
            lds_u64x2_v(hfp + 28, q0, q1);
            ana = ffma2(p0, wn[12], ana);
            anb = ffma2(p1, wn[13], anb);
            ana = ffma2(q0, wn[14], ana);
            anb = ffma2(q1, wn[15], anb);

            // ======== tail: single MUFU on the critical path ========
            float r = fmaf(0.5f, tr, 0.5f);
            float z = fmaf(0.5f, tz, 0.5f);
            u64 ns = fadd2(ana, anb);
            upk2(ns, lo, hi);
            float hn = lo + hi;                       // (+bn_h folded in init)
            float n  = tanh_mufu(fmaf(r, hn, sn));
            h = fmaf(z, h - n, n);                    // (1-z)*n + z*h

            sts_f32_v(hwp + j, h);                    // volatile: ordered before next LDS
        }
    }

    // ============ backward GRU: exactly ONE step from h=0 (elementwise) ============
    {
        float xq = xp[TT - 1];
        const float wbr = Wihb[j], wbz = Wihb[j + 32], wbn = Wihb[j + 64];
        const float cbr  = bihb[j]      + bhhb[j];
        const float cbz  = bihb[j + 32] + bhhb[j + 32];
        const float cbni = bihb[j + 64];
        const float cbnh = bhhb[j + 64];
        float r = sigm(fmaf(xq, wbr, cbr));
        float z = sigm(fmaf(xq, wbz, cbz));
        float n = tanhfast(fmaf(r, cbnh, fmaf(xq, wbn, cbni)));
        float hbk = (1.0f - z) * n;
        vbuf[warp][j]      = h;
        vbuf[warp][HH + j] = hbk;
    }
    __syncthreads();   // w1s/b1s/w2s staged + vbuf written

    // ================= MLP head: relu(v@W1.T+b1) @ W2.T + b2 -> sigmoid =========
    if (lane < 16) {
        const int u = lane;          // hidden unit
        const float b2v = __ldg(b2);
        const float* v = &vbuf[warp][0];
        float acc = b1s[u];
#pragma unroll
        for (int k = 0; k < 64; k++)
            acc = fmaf(w1s[u * 65 + k], v[k], acc);
        acc = fmaxf(acc, 0.0f);
        float tt = acc * w2s[u];
        tt += __shfl_xor_sync(0x0000ffffu, tt, 8, 16);
        tt += __shfl_xor_sync(0x0000ffffu, tt, 4, 16);
        tt += __shfl_xor_sync(0x0000ffffu, tt, 2, 16);
        tt += __shfl_xor_sync(0x0000ffffu, tt, 1, 16);
        if (u == 0) out[bb] = sigm(tt + b2v);
    }
}

extern "C" void kernel_launch(void* const* d_in, const int* in_sizes, int n_in,
                              void* d_out, int out_size) {
    const float* x    = (const float*)d_in[0];
    const float* Wihf = (const float*)d_in[1];
    const float* Whhf = (const float*)d_in[2];
    const float* bihf = (const float*)d_in[3];
    const float* bhhf = (const float*)d_in[4];
    const float* Wihb = (const float*)d_in[5];
    const float* Whhb = (const float*)d_in[6];
    const float* bihb = (const float*)d_in[7];
    const float* bhhb = (const float*)d_in[8];
    const float* W1   = (const float*)d_in[9];
    const float* b1   = (const float*)d_in[10];
    const float* W2   = (const float*)d_in[11];
    const float* b2   = (const float*)d_in[12];
    float* out = (float*)d_out;

    gru_bidir_kernel<<<NBLK, WPB * 32>>>(x, Wihf, Whhf, bihf, bhhf,
                                         Wihb, Whhb, bihb, bhhb,
                                         W1, b1, W2, b2, out);
}

// round 16
// speedup vs baseline: 1.1229x; 1.1229x over previous
#include <cuda_runtime.h>

#define NBLK 128
#define WPB  16       // warps per block -> 4 warps per SMSP
#define TT   512
#define HH   32

typedef unsigned long long u64;

__device__ __forceinline__ u64 pk2(float a, float b) {
    u64 r; asm("mov.b64 %0,{%1,%2};" : "=l"(r) : "f"(a), "f"(b)); return r;
}
__device__ __forceinline__ void upk2(u64 v, float& a, float& b) {
    asm("mov.b64 {%0,%1},%2;" : "=f"(a), "=f"(b) : "l"(v));
}
__device__ __forceinline__ u64 ffma2(u64 a, u64 b, u64 c) {
    u64 d; asm("fma.rn.f32x2 %0,%1,%2,%3;" : "=l"(d) : "l"(a), "l"(b), "l"(c)); return d;
}
__device__ __forceinline__ u64 fmul2(u64 a, u64 b) {
    u64 d; asm("mul.rn.f32x2 %0,%1,%2;" : "=l"(d) : "l"(a), "l"(b)); return d;
}
__device__ __forceinline__ u64 fadd2(u64 a, u64 b) {
    u64 d; asm("add.rn.f32x2 %0,%1,%2;" : "=l"(d) : "l"(a), "l"(b)); return d;
}
__device__ __forceinline__ float ex2f(float x) {
    float y; asm("ex2.approx.f32 %0,%1;" : "=f"(y) : "f"(x)); return y;
}
__device__ __forceinline__ float rcpf(float x) {
    float y; asm("rcp.approx.f32 %0,%1;" : "=f"(y) : "f"(x)); return y;
}
__device__ __forceinline__ float tanh_mufu(float x) {
    float y; asm("tanh.approx.f32 %0,%1;" : "=f"(y) : "f"(x)); return y;
}
// LDS.128: two u64 halves of h (non-volatile: scheduler keeps freedom)
__device__ __forceinline__ void lds_u64x2(const float* p, u64& a, u64& b) {
    unsigned sa = (unsigned)__cvta_generic_to_shared((const void*)p);
    asm volatile("ld.shared.v2.b64 {%0,%1}, [%2];" : "=l"(a), "=l"(b) : "r"(sa));
}
// accurate versions for the one-off backward step + output
__device__ __forceinline__ float sigm(float v) {
    return rcpf(1.0f + ex2f(v * -1.4426950408889634f));
}
__device__ __forceinline__ float tanhfast(float v) {
    float s = rcpf(1.0f + ex2f(v * -2.8853900817779268f));
    return fmaf(2.0f, s, -1.0f);
}

__global__ void __launch_bounds__(WPB * 32, 1)
gru_bidir_kernel(const float* __restrict__ x,
                 const float* __restrict__ Wihf, const float* __restrict__ Whhf,
                 const float* __restrict__ bihf, const float* __restrict__ bhhf,
                 const float* __restrict__ Wihb, const float* __restrict__ Whhb,
                 const float* __restrict__ bihb, const float* __restrict__ bhhb,
                 const float* __restrict__ W1,  const float* __restrict__ b1,
                 const float* __restrict__ W2,  const float* __restrict__ b2,
                 float* __restrict__ out)
{
    __shared__ float xs[WPB][TT];                          // 32 KB: x staged, 1 batch/warp
    __shared__ __align__(16) float hbuf[WPB][2][HH];       // ping-pong hidden (read as u64x2)
    __shared__ __align__(16) float vbuf[WPB][2 * HH];      // concat(h_f, h_b) for MLP
    __shared__ float  w1s[16 * 65];                        // padded stride 65 -> conflict-free
    __shared__ float  b1s[16], w2s[16];

    const int tid  = threadIdx.x;
    const int lane = tid & 31;
    const int warp = tid >> 5;
    const int bb   = blockIdx.x * WPB + warp;  // batch row owned by this warp
    const int j    = lane;                     // hidden dim owned by this lane

    // ---- stage MLP weights (block-wide) ----
    for (int i = tid; i < 16 * 64; i += WPB * 32) {
        int u = i >> 6, k = i & 63;
        w1s[u * 65 + k] = W1[i];
    }
    if (tid < 16) { b1s[tid] = b1[tid]; w2s[tid] = W2[tid]; }

    // ---- stage this warp's x row ----
    for (int i = lane; i < TT; i += 32)
        xs[warp][i] = x[bb * TT + i];

    // ---- load recurrent weights, K-packed into f32x2 pairs.
    //      r,z rows PRE-SCALED by 0.5: sigma(v) = 0.5 + 0.5*tanh(v/2) via MUFU.TANH.
    //      n rows raw: n = tanh(v) via MUFU.TANH. ----
    u64 wr[16], wz[16], wn[16];
    {
        const float2* pr = (const float2*)(Whhf + (j)      * HH);
        const float2* pz = (const float2*)(Whhf + (j + 32) * HH);
        const float2* pn = (const float2*)(Whhf + (j + 64) * HH);
#pragma unroll
        for (int k = 0; k < 16; k++) {
            float2 t0 = pr[k]; wr[k] = pk2(t0.x * 0.5f, t0.y * 0.5f);
            float2 t1 = pz[k]; wz[k] = pk2(t1.x * 0.5f, t1.y * 0.5f);
            float2 t2 = pn[k]; wn[k] = pk2(t2.x, t2.y);
        }
    }
    const float wxr = Wihf[j] * 0.5f, wxz = Wihf[j + 32] * 0.5f, wxn = Wihf[j + 64];
    const float br   = (bihf[j]      + bhhf[j])      * 0.5f;
    const float bz   = (bihf[j + 32] + bhhf[j + 32]) * 0.5f;
    const float bn_i = bihf[j + 64];     // input-side n bias (outside r*)
    const float bn_h = bhhf[j + 64];     // hidden-side n bias (inside r*)

    // ---- init hidden state ----
    float h = 0.f;
    hbuf[warp][0][j] = 0.f;
    __syncwarp();

    // ---- DESYNC: stagger warps within the SMSP by a serial FADD chain
    //      (warp&3)*16 links * lat4 = 0/64/128/192-cyc phase offsets,
    //      so the 4 warps' gate tails interleave instead of colliding. ----
    {
        float dly = 1.0f;
        int links = (warp & 3) * 16;
        for (int i = 0; i < links; i++)
            asm volatile("add.f32 %0, %0, 0f00000000;" : "+f"(dly));
        h *= (dly - dly + 1.0f) - 1.0f + 1.0f;  // dependency kept, value neutral (h stays 0)
        h = 0.0f * dly + h;                     // belt-and-braces: still exactly 0
    }

    const float* xp = &xs[warp][0];
    float* const hb0 = &hbuf[warp][0][0];
    float* const hb1 = &hbuf[warp][1][0];

    // ================= forward GRU scan (unrolled x2 over ping-pong) =================
#pragma unroll 1
    for (int t = 0; t < TT; t += 2) {
#pragma unroll
        for (int half = 0; half < 2; half++) {
            const float* hfp = half ? hb1 : hb0;
            float*       hwp = half ? hb0 : hb1;
            float xv = xp[t + half];
            float sr = fmaf(xv, wxr, br);     // scaled 0.5
            float sz = fmaf(xv, wxz, bz);     // scaled 0.5
            float sn = fmaf(xv, wxn, bn_i);   // raw

            // ---- phase 1: r gate FIRST (2 sub-chains) so its MUFU chain
            //      retires while the z/n FFMA2 chains issue ----
            u64 p0, p1;
            lds_u64x2(hfp + 0, p0, p1);
            u64 ara = ffma2(p0, wr[0], pk2(sr, 0.f));
            u64 arb = fmul2(p1, wr[1]);
#pragma unroll
            for (int k = 1; k < 8; k++) {
                lds_u64x2(hfp + 4 * k, p0, p1);
                ara = ffma2(p0, wr[2 * k],     ara);
                arb = ffma2(p1, wr[2 * k + 1], arb);
            }
            float r;
            {
                u64 s = fadd2(ara, arb);
                float lo, hi; upk2(s, lo, hi);
                r = fmaf(0.5f, tanh_mufu(lo + hi), 0.5f);
            }

            // ---- phase 2: z,n gates ----
            lds_u64x2(hfp + 0, p0, p1);
            u64 az = ffma2(p0, wz[0], pk2(sz, 0.f));
            u64 an = ffma2(p0, wn[0], pk2(bn_h, 0.f));
            az = ffma2(p1, wz[1], az);
            an = ffma2(p1, wn[1], an);
#pragma unroll
            for (int k = 1; k < 8; k++) {
                lds_u64x2(hfp + 4 * k, p0, p1);
                az = ffma2(p0, wz[2 * k], az);
                an = ffma2(p0, wn[2 * k], an);
                az = ffma2(p1, wz[2 * k + 1], az);
                an = ffma2(p1, wn[2 * k + 1], an);
            }
            float lo, hi;
            upk2(az, lo, hi);
            float z = fmaf(0.5f, tanh_mufu(lo + hi), 0.5f);
            upk2(an, lo, hi);
            float hn = lo + hi;                       // raw hidden n-part (+bn_h folded)
            float n  = tanh_mufu(fmaf(r, hn, sn));    // MUFU tanh for n
            h = fmaf(z, h - n, n);                    // (1-z)*n + z*h

            hwp[j] = h;
            __syncwarp();
        }
    }

    // ============ backward GRU: exactly ONE step from h=0 (elementwise) ============
    {
        float xq = xp[TT - 1];
        const float wbr = Wihb[j], wbz = Wihb[j + 32], wbn = Wihb[j + 64];
        const float cbr  = bihb[j]      + bhhb[j];
        const float cbz  = bihb[j + 32] + bhhb[j + 32];
        const float cbni = bihb[j + 64];
        const float cbnh = bhhb[j + 64];
        float r = sigm(fmaf(xq, wbr, cbr));
        float z = sigm(fmaf(xq, wbz, cbz));
        float n = tanhfast(fmaf(r, cbnh, fmaf(xq, wbn, cbni)));
        float hbk = (1.0f - z) * n;
        vbuf[warp][j]      = h;
        vbuf[warp][HH + j] = hbk;
    }
    __syncthreads();   // w1s/b1s/w2s staged + vbuf written

    // ================= MLP head: relu(v@W1.T+b1) @ W2.T + b2 -> sigmoid =========
    if (lane < 16) {
        const int u = lane;          // hidden unit
        const float b2v = __ldg(b2);
        const float* v = &vbuf[warp][0];
        float acc = b1s[u];
#pragma unroll
        for (int k = 0; k < 64; k++)
            acc = fmaf(w1s[u * 65 + k], v[k], acc);
        acc = fmaxf(acc, 0.0f);
        float tt = acc * w2s[u];
        tt += __shfl_xor_sync(0x0000ffffu, tt, 8, 16);
        tt += __shfl_xor_sync(0x0000ffffu, tt, 4, 16);
        tt += __shfl_xor_sync(0x0000ffffu, tt, 2, 16);
        tt += __shfl_xor_sync(0x0000ffffu, tt, 1, 16);
        if (u == 0) out[bb] = sigm(tt + b2v);
    }
}

extern "C" void kernel_launch(void* const* d_in, const int* in_sizes, int n_in,
                              void* d_out, int out_size) {
    const float* x    = (const float*)d_in[0];
    const float* Wihf = (const float*)d_in[1];
    const float* Whhf = (const float*)d_in[2];
    const float* bihf = (const float*)d_in[3];
    const float* bhhf = (const float*)d_in[4];
    const float* Wihb = (const float*)d_in[5];
    const float* Whhb = (const float*)d_in[6];
    const float* bihb = (const float*)d_in[7];
    const float* bhhb = (const float*)d_in[8];
    const float* W1   = (const float*)d_in[9];
    const float* b1   = (const float*)d_in[10];
    const float* W2   = (const float*)d_in[11];
    const float* b2   = (const float*)d_in[12];
    float* out = (float*)d_out;

    gru_bidir_kernel<<<NBLK, WPB * 32>>>(x, Wihf, Whhf, bihf, bhhf,
                                         Wihb, Whhb, bihb, bhhb,
                                         W1, b1, W2, b2, out);
}